// round 8
// baseline (speedup 1.0000x reference)
#include <cuda_runtime.h>
#include <math.h>

// Chamfer distance, B=4, N=M=8192, 3D — SYMMETRIC single-evaluation, MOV-purged.
// d computed ONCE per unordered pair; row-mins (dist1) and col-mins (dist2)
// both harvested. Deferred argmin via u64 keys (dist_bits<<32 | group_base):
// d >= 0 so float bit order == unsigned order; u64 min = lexicographic
// (dist, group) min = exact first-occurrence tie-break. Finalize recomputes
// the winning group with IDENTICAL packed ops and recovers the in-group index
// from its own registers (proven rel_err==0.0 in R7).
//
// d_out (float32): dist1[B*N] | dist2[B*M] | idx1[B*N] | idx2[B*M]

#define BATCH 4
#define NPTS  8192
#define TR 128          // tile rows (xyz1 points)
#define TC 128          // tile cols (xyz2 points)
#define TB 128          // threads: 16 (tx, col groups of 8) x 8 (ty, row groups of 16)
#define RPT 16
#define CPT 8

typedef unsigned long long u64;
typedef unsigned int u32;

__device__ u64 g_row[BATCH * NPTS];   // per xyz1 point: (best_d_bits<<32)|colgroup
__device__ u64 g_col[BATCH * NPTS];   // per xyz2 point: (best_d_bits<<32)|rowgroup

__device__ __forceinline__ void unpack2(float& lo, float& hi, u64 v) {
    asm("mov.b64 {%0, %1}, %2;" : "=f"(lo), "=f"(hi) : "l"(v));
}
__device__ __forceinline__ u64 pack2(float lo, float hi) {
    u64 r;
    asm("mov.b64 %0, {%1, %2};" : "=l"(r) : "f"(lo), "f"(hi));
    return r;
}
__device__ __forceinline__ u64 add2(u64 a, u64 b) {
    u64 r;
    asm("add.rn.f32x2 %0, %1, %2;" : "=l"(r) : "l"(a), "l"(b));
    return r;
}
__device__ __forceinline__ u64 mul2(u64 a, u64 b) {
    u64 r;
    asm("mul.rn.f32x2 %0, %1, %2;" : "=l"(r) : "l"(a), "l"(b));
    return r;
}
// Fused ((dx*dx + dy*dy) + dz*dz) per-lane rn (NO FMA), results as scalar pair.
// Single asm block lets ptxas allocate the packed temp onto {lo,hi} (elide movs).
__device__ __forceinline__ void dist2f(float& lo, float& hi, u64 dx, u64 dy, u64 dz) {
    asm("{\n\t"
        ".reg .b64 a, b, c;\n\t"
        "mul.rn.f32x2 a, %2, %2;\n\t"
        "mul.rn.f32x2 b, %3, %3;\n\t"
        "mul.rn.f32x2 c, %4, %4;\n\t"
        "add.rn.f32x2 a, a, b;\n\t"
        "add.rn.f32x2 a, a, c;\n\t"
        "mov.b64 {%0, %1}, a;\n\t"
        "}" : "=f"(lo), "=f"(hi) : "l"(dx), "l"(dy), "l"(dz));
}
__device__ __forceinline__ float negf(float x) {
    return __int_as_float(__float_as_int(x) ^ 0x80000000);
}
__device__ __forceinline__ u64 mkkey(float d, u32 g) {
    u64 r;   // hi = dist bits, lo = group: single 64-bit pack
    asm("mov.b64 %0, {%1, %2};" : "=l"(r) : "r"(g), "r"((u32)__float_as_int(d)));
    return r;
}

// ---------------------------------------------------------------- init
__global__ void init_kernel() {
    int i = blockIdx.x * blockDim.x + threadIdx.x;
    if (i < BATCH * NPTS) {
        g_row[i] = ~0ull;
        g_col[i] = ~0ull;
    }
}

// ---------------------------------------------------------------- tiles
__global__ __launch_bounds__(TB, 7) void tile_kernel(
    const float* __restrict__ xyz1,
    const float* __restrict__ xyz2)
{
    __shared__ __align__(16) u64 srd[3][TR];    // row coords, DUPLICATED lanes
    __shared__ __align__(16) float sc[3][TC];   // NEGATED col coords
    __shared__ u64 srow[TR][16];                // per-row keys by tx
    __shared__ u64 scol[TC][8];                 // per-col keys by ty

    const int b       = blockIdx.z;
    const int rowbase = blockIdx.y * TR;
    const int colbase = blockIdx.x * TC;
    const int tid = threadIdx.x;
    const int tx  = tid & 15;       // col group: cols tx*8 .. tx*8+7
    const int ty  = tid >> 4;       // row group: rows ty*16 .. ty*16+15

    // Stage tile coords (one row pt + one col pt per thread).
    {
        const float* p1 = xyz1 + ((size_t)b * NPTS + rowbase + tid) * 3;
        const float* p2 = xyz2 + ((size_t)b * NPTS + colbase + tid) * 3;
        srd[0][tid] = pack2(p1[0], p1[0]);
        srd[1][tid] = pack2(p1[1], p1[1]);
        srd[2][tid] = pack2(p1[2], p1[2]);
        sc[0][tid] = negf(p2[0]);
        sc[1][tid] = negf(p2[1]);
        sc[2][tid] = negf(p2[2]);
    }
    __syncthreads();

    // This thread's 8 negated col coords, packed as 4 f32x2 per coord.
    u64 cx[4], cy[4], cz[4];
    {
        const ulonglong2* vx = (const ulonglong2*)(&sc[0][tx * CPT]);
        const ulonglong2* vy = (const ulonglong2*)(&sc[1][tx * CPT]);
        const ulonglong2* vz = (const ulonglong2*)(&sc[2][tx * CPT]);
        ulonglong2 a, c;
        a = vx[0]; c = vx[1]; cx[0] = a.x; cx[1] = a.y; cx[2] = c.x; cx[3] = c.y;
        a = vy[0]; c = vy[1]; cy[0] = a.x; cy[1] = a.y; cy[2] = c.x; cy[3] = c.y;
        a = vz[0]; c = vz[1]; cz[0] = a.x; cz[1] = a.y; cz[2] = c.x; cz[3] = c.y;
    }

    float colmin[CPT];
    #pragma unroll
    for (int k = 0; k < CPT; ++k) colmin[k] = INFINITY;

    const u32 colgroup = (u32)(colbase + tx * CPT);
    const u32 rowgroup = (u32)(rowbase + ty * RPT);

    #pragma unroll 4
    for (int ri = 0; ri < RPT; ++ri) {
        const int r = ty * RPT + ri;
        const u64 pxx = srd[0][r];   // LDS.64, already duplicated
        const u64 pyy = srd[1][r];
        const u64 pzz = srd[2][r];

        float d0, d1, d2, d3, d4, d5, d6, d7;
        dist2f(d0, d1, add2(pxx, cx[0]), add2(pyy, cy[0]), add2(pzz, cz[0]));
        dist2f(d2, d3, add2(pxx, cx[1]), add2(pyy, cy[1]), add2(pzz, cz[1]));
        dist2f(d4, d5, add2(pxx, cx[2]), add2(pyy, cy[2]), add2(pzz, cz[2]));
        dist2f(d6, d7, add2(pxx, cx[3]), add2(pyy, cy[3]), add2(pzz, cz[3]));

        // Column running mins (value only; row recovered in finalize).
        colmin[0] = fminf(colmin[0], d0);
        colmin[1] = fminf(colmin[1], d1);
        colmin[2] = fminf(colmin[2], d2);
        colmin[3] = fminf(colmin[3], d3);
        colmin[4] = fminf(colmin[4], d4);
        colmin[5] = fminf(colmin[5], d5);
        colmin[6] = fminf(colmin[6], d6);
        colmin[7] = fminf(colmin[7], d7);

        // Row min over this thread's 8 cols -> deferred key.
        const float m = fminf(fminf(fminf(d0, d1), fminf(d2, d3)),
                              fminf(fminf(d4, d5), fminf(d6, d7)));
        srow[r][tx] = mkkey(m, colgroup);
    }

    // Column keys.
    #pragma unroll
    for (int k = 0; k < CPT; ++k)
        scol[tx * CPT + k][ty] = mkkey(colmin[k], rowgroup);

    __syncthreads();

    // Block-level reductions + one global RED per row / col.
    {
        u64 v = srow[tid][0];
        #pragma unroll
        for (int i = 1; i < 16; ++i) v = (srow[tid][i] < v) ? srow[tid][i] : v;
        atomicMin(&g_row[(size_t)b * NPTS + rowbase + tid], v);
    }
    {
        u64 v = scol[tid][0];
        #pragma unroll
        for (int i = 1; i < 8; ++i) v = (scol[tid][i] < v) ? scol[tid][i] : v;
        atomicMin(&g_col[(size_t)b * NPTS + colbase + tid], v);
    }
}

// ---------------------------------------------------------------- finalize
__global__ __launch_bounds__(128) void finalize_kernel(
    const float* __restrict__ xyz1,
    const float* __restrict__ xyz2,
    float* __restrict__ out)
{
    const int idx = blockIdx.x * 128 + threadIdx.x;   // 0 .. 65535
    const int half = BATCH * NPTS;                    // 32768

    if (idx < half) {
        // Row side: dist1/idx1 for xyz1 point (b, r), candidates = xyz2.
        const int b = idx >> 13, r = idx & (NPTS - 1);
        const u32 j0 = (u32)g_row[idx];   // winning col group base (multiple of 8)

        const float* p = xyz1 + ((size_t)b * NPTS + r) * 3;
        const u64 pxx = pack2(p[0], p[0]);
        const u64 pyy = pack2(p[1], p[1]);
        const u64 pzz = pack2(p[2], p[2]);

        float d[8];
        #pragma unroll
        for (int kk = 0; kk < 4; ++kk) {
            const float* c0 = xyz2 + ((size_t)b * NPTS + j0 + 2 * kk) * 3;
            const float* c1 = c0 + 3;
            u64 dxx = add2(pxx, pack2(negf(c0[0]), negf(c1[0])));
            u64 dyy = add2(pyy, pack2(negf(c0[1]), negf(c1[1])));
            u64 dzz = add2(pzz, pack2(negf(c0[2]), negf(c1[2])));
            dist2f(d[2 * kk], d[2 * kk + 1],
                   dxx, dyy, dzz);
        }
        const float m = fminf(fminf(fminf(d[0], d[1]), fminf(d[2], d[3])),
                              fminf(fminf(d[4], d[5]), fminf(d[6], d[7])));
        int s = 7;                        // descending scan: lowest match wins
        if (d[6] == m) s = 6;
        if (d[5] == m) s = 5;
        if (d[4] == m) s = 4;
        if (d[3] == m) s = 3;
        if (d[2] == m) s = 2;
        if (d[1] == m) s = 1;
        if (d[0] == m) s = 0;

        out[idx]            = m;                      // dist1
        out[2 * half + idx] = (float)(j0 + s);        // idx1
    } else {
        // Col side: dist2/idx2 for xyz2 point (b, j), candidates = xyz1.
        const int o = idx - half;
        const int b = o >> 13, j = o & (NPTS - 1);
        const u32 r0 = (u32)g_col[o];     // winning row group base (multiple of 16)

        const float* c = xyz2 + ((size_t)b * NPTS + j) * 3;
        const u64 ncx = pack2(negf(c[0]), negf(c[0]));
        const u64 ncy = pack2(negf(c[1]), negf(c[1]));
        const u64 ncz = pack2(negf(c[2]), negf(c[2]));

        float d[16];
        #pragma unroll
        for (int kk = 0; kk < 8; ++kk) {
            const float* p0 = xyz1 + ((size_t)b * NPTS + r0 + 2 * kk) * 3;
            const float* p1 = p0 + 3;
            u64 dxx = add2(pack2(p0[0], p1[0]), ncx);
            u64 dyy = add2(pack2(p0[1], p1[1]), ncy);
            u64 dzz = add2(pack2(p0[2], p1[2]), ncz);
            dist2f(d[2 * kk], d[2 * kk + 1], dxx, dyy, dzz);
        }
        float m = d[0];
        #pragma unroll
        for (int k = 1; k < 16; ++k) m = fminf(m, d[k]);
        int s = 15;
        #pragma unroll
        for (int k = 14; k >= 0; --k)
            if (d[k] == m) s = k;

        out[half + o]     = m;                        // dist2
        out[3 * half + o] = (float)(r0 + s);          // idx2
    }
}

// ---------------------------------------------------------------- launch
extern "C" void kernel_launch(void* const* d_in, const int* in_sizes, int n_in,
                              void* d_out, int out_size)
{
    const float* xyz1 = (const float*)d_in[0];  // [4, 8192, 3]
    const float* xyz2 = (const float*)d_in[1];  // [4, 8192, 3]
    float* out = (float*)d_out;

    init_kernel<<<(BATCH * NPTS + 255) / 256, 256>>>();

    dim3 grid(NPTS / TC, NPTS / TR, BATCH);   // (64, 64, 4)
    tile_kernel<<<grid, TB>>>(xyz1, xyz2);

    finalize_kernel<<<(2 * BATCH * NPTS) / 128, 128>>>(xyz1, xyz2, out);
}

// round 9
// speedup vs baseline: 1.0860x; 1.0860x over previous
#include <cuda_runtime.h>
#include <math.h>

// Chamfer distance, B=4, N=M=8192, 3D — SYMMETRIC, chunk-looped blocks.
// Each unordered pair evaluated ONCE; row-mins (dist1) and col-mins (dist2)
// harvested together. Deferred argmin via u64 keys (dist_bits<<32 | group):
// d >= 0 so float bit order == unsigned order; u64 min = lexicographic
// (dist, group) min = exact first-occurrence tie-break. Finalize recomputes
// the winning group with identical packed ops and recovers the in-group index
// from its own registers (rel_err==0.0 proven in R7/R8).
//
// d_out (float32): dist1[B*N] | dist2[B*M] | idx1[B*N] | idx2[B*M]

#define BATCH 4
#define NPTS  8192
#define TR 128           // rows per block (xyz1 points)
#define TCC 128          // cols per chunk (xyz2 points)
#define NCHUNK 16        // chunks per block -> 2048 cols per block
#define COLSPLIT 4       // NPTS / (TCC*NCHUNK)
#define TB 128           // 16 (tx: col groups of 8) x 8 (ty: row groups of 16)
#define RPT 16
#define CPT 8

typedef unsigned long long u64;
typedef unsigned int u32;

__device__ u64 g_row[BATCH * NPTS];   // per xyz1 point: (d_bits<<32)|colgroup(8)
__device__ u64 g_col[BATCH * NPTS];   // per xyz2 point: (d_bits<<32)|rowgroup(16)

__device__ __forceinline__ void unpack2(float& lo, float& hi, u64 v) {
    asm("mov.b64 {%0, %1}, %2;" : "=f"(lo), "=f"(hi) : "l"(v));
}
__device__ __forceinline__ u64 pack2(float lo, float hi) {
    u64 r;
    asm("mov.b64 %0, {%1, %2};" : "=l"(r) : "f"(lo), "f"(hi));
    return r;
}
__device__ __forceinline__ u64 add2(u64 a, u64 b) {
    u64 r;
    asm("add.rn.f32x2 %0, %1, %2;" : "=l"(r) : "l"(a), "l"(b));
    return r;
}
__device__ __forceinline__ u64 mul2(u64 a, u64 b) {
    u64 r;
    asm("mul.rn.f32x2 %0, %1, %2;" : "=l"(r) : "l"(a), "l"(b));
    return r;
}
__device__ __forceinline__ float negf(float x) {
    return __int_as_float(__float_as_int(x) ^ 0x80000000);
}
__device__ __forceinline__ u64 mkkey(float d, u32 g) {
    u64 r;   // hi = dist bits, lo = group base
    asm("mov.b64 %0, {%1, %2};" : "=l"(r) : "r"(g), "r"((u32)__float_as_int(d)));
    return r;
}

// ---------------------------------------------------------------- init
__global__ void init_kernel() {
    int i = blockIdx.x * blockDim.x + threadIdx.x;
    if (i < BATCH * NPTS) {
        g_row[i] = ~0ull;
        g_col[i] = ~0ull;
    }
}

// ---------------------------------------------------------------- tiles
__global__ __launch_bounds__(TB) void tile_kernel(
    const float* __restrict__ xyz1,
    const float* __restrict__ xyz2)
{
    __shared__ __align__(16) u64 srd[3][TR];    // row coords, duplicated lanes
    __shared__ __align__(16) float sc[3][TCC];  // NEGATED col coords (per chunk)
    __shared__ u64 srow[TR][16];                // final row reduction by tx
    __shared__ u64 scol[TCC][8];                // per-chunk col reduction by ty

    const int b        = blockIdx.z;
    const int rowbase  = blockIdx.x * TR;
    const int colsplit = blockIdx.y;            // 0..3
    const int tid = threadIdx.x;
    const int tx  = tid & 15;                   // cols tx*8 .. tx*8+7 of chunk
    const int ty  = tid >> 4;                   // rows ty*16 .. ty*16+15

    // Stage the block's 128 row points once (duplicated u64 lanes).
    {
        const float* p1 = xyz1 + ((size_t)b * NPTS + rowbase + tid) * 3;
        srd[0][tid] = pack2(p1[0], p1[0]);
        srd[1][tid] = pack2(p1[1], p1[1]);
        srd[2][tid] = pack2(p1[2], p1[2]);
    }

    const u32 rowgroup = (u32)(rowbase + ty * RPT);

    // Thread-private running row keys (slot (r, tx) is thread-owned).
    u64 rowkey[RPT];
    #pragma unroll
    for (int i = 0; i < RPT; ++i) rowkey[i] = ~0ull;

    for (int chunk = 0; chunk < NCHUNK; ++chunk) {
        const int colbase = (colsplit * NCHUNK + chunk) * TCC;

        // Stage this chunk's 128 col points, negated.
        {
            const float* p2 = xyz2 + ((size_t)b * NPTS + colbase + tid) * 3;
            sc[0][tid] = negf(p2[0]);
            sc[1][tid] = negf(p2[1]);
            sc[2][tid] = negf(p2[2]);
        }
        __syncthreads();   // (also covers srd on first iter)

        // This thread's 8 negated col coords as 4 f32x2 per coordinate.
        u64 cx[4], cy[4], cz[4];
        {
            const ulonglong2* vx = (const ulonglong2*)(&sc[0][tx * CPT]);
            const ulonglong2* vy = (const ulonglong2*)(&sc[1][tx * CPT]);
            const ulonglong2* vz = (const ulonglong2*)(&sc[2][tx * CPT]);
            ulonglong2 a, c;
            a = vx[0]; c = vx[1]; cx[0]=a.x; cx[1]=a.y; cx[2]=c.x; cx[3]=c.y;
            a = vy[0]; c = vy[1]; cy[0]=a.x; cy[1]=a.y; cy[2]=c.x; cy[3]=c.y;
            a = vz[0]; c = vz[1]; cz[0]=a.x; cz[1]=a.y; cz[2]=c.x; cz[3]=c.y;
        }

        float colmin[CPT];
        #pragma unroll
        for (int k = 0; k < CPT; ++k) colmin[k] = INFINITY;

        const u32 colgroup = (u32)(colbase + tx * CPT);

        #pragma unroll 4
        for (int ri = 0; ri < RPT; ++ri) {
            const int r = ty * RPT + ri;
            const u64 pxx = srd[0][r];
            const u64 pyy = srd[1][r];
            const u64 pzz = srd[2][r];

            // d = ((dx*dx + dy*dy) + dz*dz), per-lane rn, NO FMA (matches XLA).
            u64 dx0 = add2(pxx, cx[0]), dx1 = add2(pxx, cx[1]);
            u64 dx2 = add2(pxx, cx[2]), dx3 = add2(pxx, cx[3]);
            u64 dy0 = add2(pyy, cy[0]), dy1 = add2(pyy, cy[1]);
            u64 dy2 = add2(pyy, cy[2]), dy3 = add2(pyy, cy[3]);
            u64 dz0 = add2(pzz, cz[0]), dz1 = add2(pzz, cz[1]);
            u64 dz2 = add2(pzz, cz[2]), dz3 = add2(pzz, cz[3]);
            u64 d01 = add2(add2(mul2(dx0, dx0), mul2(dy0, dy0)), mul2(dz0, dz0));
            u64 d23 = add2(add2(mul2(dx1, dx1), mul2(dy1, dy1)), mul2(dz1, dz1));
            u64 d45 = add2(add2(mul2(dx2, dx2), mul2(dy2, dy2)), mul2(dz2, dz2));
            u64 d67 = add2(add2(mul2(dx3, dx3), mul2(dy3, dy3)), mul2(dz3, dz3));

            float d0, d1, d2, d3, d4, d5, d6, d7;
            unpack2(d0, d1, d01);
            unpack2(d2, d3, d23);
            unpack2(d4, d5, d45);
            unpack2(d6, d7, d67);

            colmin[0] = fminf(colmin[0], d0);
            colmin[1] = fminf(colmin[1], d1);
            colmin[2] = fminf(colmin[2], d2);
            colmin[3] = fminf(colmin[3], d3);
            colmin[4] = fminf(colmin[4], d4);
            colmin[5] = fminf(colmin[5], d5);
            colmin[6] = fminf(colmin[6], d6);
            colmin[7] = fminf(colmin[7], d7);

            const float m = fminf(fminf(fminf(d0, d1), fminf(d2, d3)),
                                  fminf(fminf(d4, d5), fminf(d6, d7)));
            const u64 nk = mkkey(m, colgroup);
            rowkey[ri] = (nk < rowkey[ri]) ? nk : rowkey[ri];
        }

        // Flush this chunk's column keys and reduce.
        #pragma unroll
        for (int k = 0; k < CPT; ++k)
            scol[tx * CPT + k][ty] = mkkey(colmin[k], rowgroup);
        __syncthreads();
        {
            u64 v = scol[tid][0];
            #pragma unroll
            for (int i = 1; i < 8; ++i) v = (scol[tid][i] < v) ? scol[tid][i] : v;
            atomicMin(&g_col[(size_t)b * NPTS + colbase + tid], v);
        }
        // Next chunk's scol writes happen only after the next post-stage
        // __syncthreads(), which every thread reaches after this reduce: safe.
    }

    // Final row reduction across tx.
    #pragma unroll
    for (int ri = 0; ri < RPT; ++ri)
        srow[ty * RPT + ri][tx] = rowkey[ri];
    __syncthreads();
    {
        u64 v = srow[tid][0];
        #pragma unroll
        for (int i = 1; i < 16; ++i) v = (srow[tid][i] < v) ? srow[tid][i] : v;
        atomicMin(&g_row[(size_t)b * NPTS + rowbase + tid], v);
    }
}

// ---------------------------------------------------------------- finalize
// Recompute winning group with the SAME packed ops; recover in-group argmin
// from those registers (first occurrence). Proven rel_err==0.0 (R7/R8).
__global__ __launch_bounds__(128) void finalize_kernel(
    const float* __restrict__ xyz1,
    const float* __restrict__ xyz2,
    float* __restrict__ out)
{
    const int idx = blockIdx.x * 128 + threadIdx.x;   // 0 .. 65535
    const int half = BATCH * NPTS;                    // 32768

    if (idx < half) {
        // dist1/idx1 for xyz1 point (b, r); candidates = xyz2 group of 8.
        const int b = idx >> 13, r = idx & (NPTS - 1);
        const u32 j0 = (u32)g_row[idx];

        const float* p = xyz1 + ((size_t)b * NPTS + r) * 3;
        const u64 pxx = pack2(p[0], p[0]);
        const u64 pyy = pack2(p[1], p[1]);
        const u64 pzz = pack2(p[2], p[2]);

        float d[8];
        #pragma unroll
        for (int kk = 0; kk < 4; ++kk) {
            const float* c0 = xyz2 + ((size_t)b * NPTS + j0 + 2 * kk) * 3;
            const float* c1 = c0 + 3;
            u64 dxx = add2(pxx, pack2(negf(c0[0]), negf(c1[0])));
            u64 dyy = add2(pyy, pack2(negf(c0[1]), negf(c1[1])));
            u64 dzz = add2(pzz, pack2(negf(c0[2]), negf(c1[2])));
            u64 dd  = add2(add2(mul2(dxx, dxx), mul2(dyy, dyy)), mul2(dzz, dzz));
            unpack2(d[2 * kk], d[2 * kk + 1], dd);
        }
        const float m = fminf(fminf(fminf(d[0], d[1]), fminf(d[2], d[3])),
                              fminf(fminf(d[4], d[5]), fminf(d[6], d[7])));
        int s = 7;
        if (d[6] == m) s = 6;
        if (d[5] == m) s = 5;
        if (d[4] == m) s = 4;
        if (d[3] == m) s = 3;
        if (d[2] == m) s = 2;
        if (d[1] == m) s = 1;
        if (d[0] == m) s = 0;

        out[idx]            = m;                  // dist1
        out[2 * half + idx] = (float)(j0 + s);    // idx1
    } else {
        // dist2/idx2 for xyz2 point (b, j); candidates = xyz1 group of 16.
        const int o = idx - half;
        const int b = o >> 13, j = o & (NPTS - 1);
        const u32 r0 = (u32)g_col[o];

        const float* c = xyz2 + ((size_t)b * NPTS + j) * 3;
        const u64 ncx = pack2(negf(c[0]), negf(c[0]));
        const u64 ncy = pack2(negf(c[1]), negf(c[1]));
        const u64 ncz = pack2(negf(c[2]), negf(c[2]));

        float d[16];
        #pragma unroll
        for (int kk = 0; kk < 8; ++kk) {
            const float* p0 = xyz1 + ((size_t)b * NPTS + r0 + 2 * kk) * 3;
            const float* p1 = p0 + 3;
            u64 dxx = add2(pack2(p0[0], p1[0]), ncx);
            u64 dyy = add2(pack2(p0[1], p1[1]), ncy);
            u64 dzz = add2(pack2(p0[2], p1[2]), ncz);
            u64 dd  = add2(add2(mul2(dxx, dxx), mul2(dyy, dyy)), mul2(dzz, dzz));
            unpack2(d[2 * kk], d[2 * kk + 1], dd);
        }
        float m = d[0];
        #pragma unroll
        for (int k = 1; k < 16; ++k) m = fminf(m, d[k]);
        int s = 15;
        #pragma unroll
        for (int k = 14; k >= 0; --k)
            if (d[k] == m) s = k;

        out[half + o]     = m;                    // dist2
        out[3 * half + o] = (float)(r0 + s);      // idx2
    }
}

// ---------------------------------------------------------------- launch
extern "C" void kernel_launch(void* const* d_in, const int* in_sizes, int n_in,
                              void* d_out, int out_size)
{
    const float* xyz1 = (const float*)d_in[0];  // [4, 8192, 3]
    const float* xyz2 = (const float*)d_in[1];  // [4, 8192, 3]
    float* out = (float*)d_out;

    init_kernel<<<(BATCH * NPTS + 255) / 256, 256>>>();

    dim3 grid(NPTS / TR, COLSPLIT, BATCH);   // (64, 4, 4) = 1024 blocks
    tile_kernel<<<grid, TB>>>(xyz1, xyz2);

    finalize_kernel<<<(2 * BATCH * NPTS) / 128, 128>>>(xyz1, xyz2, out);
}

// round 10
// speedup vs baseline: 1.2763x; 1.1752x over previous
#include <cuda_runtime.h>
#include <math.h>

// Chamfer distance, B=4, N=M=8192, 3D.
// d_out (float32): dist1[B*N] | dist2[B*M] | idx1[B*N] | idx2[B*M]
// R3-proven body (packed f32x2, exact rn, in-loop argmin from own registers),
// upgraded: 2 queries per thread share each candidate LDS and provide two
// independent fp chains (latency hiding at constant occupancy).
//  - 128 threads = 32 query-slots x 4 segments; thread handles queries
//    (slot, slot+32) against its 256-candidate segment per 1024-chunk.
//  - exact lexicographic (d, idx) combine across segments.

#define QPB 128
#define NQ_BLK 64          // queries per block
#define NSLOT 32           // query slots (threads per segment)
#define NSEG 4
#define CH 1024            // candidates staged per chunk
#define SEG 256            // candidates per segment per chunk

typedef unsigned long long u64;

__device__ __forceinline__ void unpack2(float& lo, float& hi, u64 v) {
    asm("mov.b64 {%0, %1}, %2;" : "=f"(lo), "=f"(hi) : "l"(v));
}
__device__ __forceinline__ u64 pack2(float lo, float hi) {
    u64 r;
    asm("mov.b64 %0, {%1, %2};" : "=l"(r) : "f"(lo), "f"(hi));
    return r;
}
__device__ __forceinline__ u64 add2(u64 a, u64 b) {
    u64 r;
    asm("add.rn.f32x2 %0, %1, %2;" : "=l"(r) : "l"(a), "l"(b));
    return r;
}
__device__ __forceinline__ u64 mul2(u64 a, u64 b) {
    u64 r;
    asm("mul.rn.f32x2 %0, %1, %2;" : "=l"(r) : "l"(a), "l"(b));
    return r;
}
__device__ __forceinline__ float negf(float x) {
    return __int_as_float(__float_as_int(x) ^ 0x80000000);
}

__global__ __launch_bounds__(QPB) void chamfer_kernel(
    const float* __restrict__ xyz1,
    const float* __restrict__ xyz2,
    float* __restrict__ out,
    int N, int M, int B)
{
    __shared__ __align__(16) float smem_f[3 * CH];   // negated SoA: x | y | z
    __shared__ float rbest[NSEG * NQ_BLK];
    __shared__ int   rbi[NSEG * NQ_BLK];

    float* sx = smem_f;
    float* sy = smem_f + CH;
    float* sz = smem_f + 2 * CH;

    const int dir = blockIdx.z;   // 0: xyz1->xyz2, 1: xyz2->xyz1
    const int b   = blockIdx.y;

    const float* q; const float* c;
    float* outd; float* outi;
    int Nq, Nc;
    if (dir == 0) {
        q = xyz1; c = xyz2; Nq = N; Nc = M;
        outd = out;
        outi = out + (size_t)B * N + (size_t)B * M;
    } else {
        q = xyz2; c = xyz1; Nq = M; Nc = N;
        outd = out + (size_t)B * N;
        outi = out + (size_t)B * N + (size_t)B * M + (size_t)B * N;
    }

    const int tid  = threadIdx.x;
    const int slot = tid & (NSLOT - 1);   // 0..31
    const int seg  = tid >> 5;            // 0..3
    const int qi0  = blockIdx.x * NQ_BLK + slot;        // query A
    const int qi1  = qi0 + NSLOT;                       // query B

    const float* qa = q + ((size_t)b * Nq + qi0) * 3;
    const float* qbp = q + ((size_t)b * Nq + qi1) * 3;
    const float* cb = c + (size_t)b * Nc * 3;

    const u64 paxx = pack2(qa[0], qa[0]);
    const u64 payy = pack2(qa[1], qa[1]);
    const u64 pazz = pack2(qa[2], qa[2]);
    const u64 pbxx = pack2(qbp[0], qbp[0]);
    const u64 pbyy = pack2(qbp[1], qbp[1]);
    const u64 pbzz = pack2(qbp[2], qbp[2]);

    // Segment views of the staged chunk (64-bit lanes, LDS.128 pairs).
    const ulonglong2* sxv = (const ulonglong2*)(sx + seg * SEG);
    const ulonglong2* syv = (const ulonglong2*)(sy + seg * SEG);
    const ulonglong2* szv = (const ulonglong2*)(sz + seg * SEG);

    float bestA = INFINITY, bestB = INFINITY;
    int   biA = 0, biB = 0;

    for (int base = 0; base < Nc; base += CH) {
        __syncthreads();
        // Stage CH candidates, sign-flipped (XOR, exact negate).
        for (int t = tid; t < CH; t += QPB) {
            const float* p = cb + (size_t)(base + t) * 3;
            sx[t] = negf(p[0]);
            sy[t] = negf(p[1]);
            sz[t] = negf(p[2]);
        }
        __syncthreads();

        const int segbase = base + seg * SEG;

        #pragma unroll 2
        for (int g = 0; g < SEG / 8; ++g) {
            const ulonglong2 X0 = sxv[2 * g], X1 = sxv[2 * g + 1];
            const ulonglong2 Y0 = syv[2 * g], Y1 = syv[2 * g + 1];
            const ulonglong2 Z0 = szv[2 * g], Z1 = szv[2 * g + 1];
            const int jb = segbase + g * 8;

            // ---- query A ----
            {
                u64 dx0 = add2(paxx, X0.x), dx1 = add2(paxx, X0.y);
                u64 dx2 = add2(paxx, X1.x), dx3 = add2(paxx, X1.y);
                u64 dy0 = add2(payy, Y0.x), dy1 = add2(payy, Y0.y);
                u64 dy2 = add2(payy, Y1.x), dy3 = add2(payy, Y1.y);
                u64 dz0 = add2(pazz, Z0.x), dz1 = add2(pazz, Z0.y);
                u64 dz2 = add2(pazz, Z1.x), dz3 = add2(pazz, Z1.y);
                u64 d01 = add2(add2(mul2(dx0, dx0), mul2(dy0, dy0)), mul2(dz0, dz0));
                u64 d23 = add2(add2(mul2(dx1, dx1), mul2(dy1, dy1)), mul2(dz1, dz1));
                u64 d45 = add2(add2(mul2(dx2, dx2), mul2(dy2, dy2)), mul2(dz2, dz2));
                u64 d67 = add2(add2(mul2(dx3, dx3), mul2(dy3, dy3)), mul2(dz3, dz3));

                float d0, d1, d2, d3, d4, d5, d6, d7;
                unpack2(d0, d1, d01);
                unpack2(d2, d3, d23);
                unpack2(d4, d5, d45);
                unpack2(d6, d7, d67);
                const float m = fminf(fminf(fminf(d0, d1), fminf(d2, d3)),
                                      fminf(fminf(d4, d5), fminf(d6, d7)));
                if (m < bestA) {   // strict <: earlier groups win ties
                    bestA = m;
                    int s = jb + 7;   // descending scan: lowest match wins
                    if (d6 == m) s = jb + 6;
                    if (d5 == m) s = jb + 5;
                    if (d4 == m) s = jb + 4;
                    if (d3 == m) s = jb + 3;
                    if (d2 == m) s = jb + 2;
                    if (d1 == m) s = jb + 1;
                    if (d0 == m) s = jb;
                    biA = s;
                }
            }

            // ---- query B ----
            {
                u64 dx0 = add2(pbxx, X0.x), dx1 = add2(pbxx, X0.y);
                u64 dx2 = add2(pbxx, X1.x), dx3 = add2(pbxx, X1.y);
                u64 dy0 = add2(pbyy, Y0.x), dy1 = add2(pbyy, Y0.y);
                u64 dy2 = add2(pbyy, Y1.x), dy3 = add2(pbyy, Y1.y);
                u64 dz0 = add2(pbzz, Z0.x), dz1 = add2(pbzz, Z0.y);
                u64 dz2 = add2(pbzz, Z1.x), dz3 = add2(pbzz, Z1.y);
                u64 d01 = add2(add2(mul2(dx0, dx0), mul2(dy0, dy0)), mul2(dz0, dz0));
                u64 d23 = add2(add2(mul2(dx1, dx1), mul2(dy1, dy1)), mul2(dz1, dz1));
                u64 d45 = add2(add2(mul2(dx2, dx2), mul2(dy2, dy2)), mul2(dz2, dz2));
                u64 d67 = add2(add2(mul2(dx3, dx3), mul2(dy3, dy3)), mul2(dz3, dz3));

                float d0, d1, d2, d3, d4, d5, d6, d7;
                unpack2(d0, d1, d01);
                unpack2(d2, d3, d23);
                unpack2(d4, d5, d45);
                unpack2(d6, d7, d67);
                const float m = fminf(fminf(fminf(d0, d1), fminf(d2, d3)),
                                      fminf(fminf(d4, d5), fminf(d6, d7)));
                if (m < bestB) {
                    bestB = m;
                    int s = jb + 7;
                    if (d6 == m) s = jb + 6;
                    if (d5 == m) s = jb + 5;
                    if (d4 == m) s = jb + 4;
                    if (d3 == m) s = jb + 3;
                    if (d2 == m) s = jb + 2;
                    if (d1 == m) s = jb + 1;
                    if (d0 == m) s = jb;
                    biB = s;
                }
            }
        }
    }

    // Per-segment results: local query id = slot (A) and slot+32 (B).
    rbest[seg * NQ_BLK + slot]         = bestA;
    rbi[seg * NQ_BLK + slot]           = biA;
    rbest[seg * NQ_BLK + slot + NSLOT] = bestB;
    rbi[seg * NQ_BLK + slot + NSLOT]   = biB;
    __syncthreads();

    // Combine 4 segments per query: lexicographic (d, idx) min == first occurrence.
    if (tid < NQ_BLK) {
        float bd  = rbest[tid];
        int   bix = rbi[tid];
        #pragma unroll
        for (int s = 1; s < NSEG; ++s) {
            const float od = rbest[s * NQ_BLK + tid];
            const int   oi = rbi[s * NQ_BLK + tid];
            if (od < bd || (od == bd && oi < bix)) { bd = od; bix = oi; }
        }
        const int qi = blockIdx.x * NQ_BLK + tid;
        outd[(size_t)b * Nq + qi] = bd;
        outi[(size_t)b * Nq + qi] = (float)bix;   // <= 8191, exact in fp32
    }
}

extern "C" void kernel_launch(void* const* d_in, const int* in_sizes, int n_in,
                              void* d_out, int out_size)
{
    const float* xyz1 = (const float*)d_in[0];  // [4, 8192, 3]
    const float* xyz2 = (const float*)d_in[1];  // [4, 8192, 3]
    float* out = (float*)d_out;

    const int B = 4;
    const int N = in_sizes[0] / (B * 3);  // 8192
    const int M = in_sizes[1] / (B * 3);  // 8192

    dim3 block(QPB, 1, 1);
    dim3 grid(N / NQ_BLK, B, 2);   // 1024 blocks x 128 threads
    chamfer_kernel<<<grid, block>>>(xyz1, xyz2, out, N, M, B);
}